// round 6
// baseline (speedup 1.0000x reference)
#include <cuda_runtime.h>

#define HW 16384
#define WD 128

typedef unsigned long long u64;

// Scratch (allocation-free rule: __device__ globals)
__device__ float g_est1[2 * 128 * HW];   // 16 MB
__device__ float g_est2[2 * 128 * HW];   // 16 MB
__device__ float g_off [2 * 18  * HW];   // 2.25 MB
__device__ float g_wt  [9 * 128 * 128];  // w_def transposed to [k][c][o]
__device__ float g_dmy [128];

// ---- packed fp32x2 helpers -------------------------------------------------
__device__ __forceinline__ u64 pk(float lo, float hi) {
    u64 r; asm("mov.b64 %0, {%1, %2};" : "=l"(r) : "f"(lo), "f"(hi)); return r;
}
__device__ __forceinline__ void upk(u64 v, float& lo, float& hi) {
    asm("mov.b64 {%0, %1}, %2;" : "=f"(lo), "=f"(hi) : "l"(v));
}
__device__ __forceinline__ u64 fma2(u64 a, u64 b, u64 c) {
    u64 d; asm("fma.rn.f32x2 %0, %1, %2, %3;" : "=l"(d) : "l"(a), "l"(b), "l"(c));
    return d;
}

// ---- cp.async helpers --------------------------------------------------------
__device__ __forceinline__ unsigned sm32(const void* p) {
    return (unsigned)__cvta_generic_to_shared(p);
}
__device__ __forceinline__ void cpa16(unsigned s, const float* g, bool v) {
    asm volatile("cp.async.cg.shared.global [%0], [%1], 16, %2;"
                 :: "r"(s), "l"(g), "r"(v ? 16u : 0u));
}
__device__ __forceinline__ void cpa_commit() {
    asm volatile("cp.async.commit_group;");
}
template <int N>
__device__ __forceinline__ void cpa_wait() {
    asm volatile("cp.async.wait_group %0;" :: "n"(N));
}

// ---------------------------------------------------------------------------
// Direct 3x3 conv, stride 1, pad 1, NCHW, H=W=128, fp32x2 math.
// 3-stage cp.async ring (2 channels/stage, distance 2, one barrier/stage).
// Rolling 2-row input-pair window (20 P regs instead of 40) -> 6 CTAs/SM.
// Weights repacked as [o][ky][4] u64 so each (o,ky) is LDS.128 + LDS.64.
// Block: 128 threads; output tile 16(h) x 64(w); thread: 2 rows x 4 cols;
// OC_B=4 output channels register-blocked.
// ---------------------------------------------------------------------------
template <int C_IN, int OC_B, bool RELU, bool CONCAT>
__global__ __launch_bounds__(128, 6) void conv3x3_k(
    const float* __restrict__ in0, const float* __restrict__ in1,
    const float* __restrict__ wt, float* __restrict__ out,
    int C_out, int n_ocb)
{
    // stage buffers: [3 stages][2 ch][18 rows * 72 floats]
    __shared__ __align__(16) float st[3][2 * 1296];
    __shared__ __align__(16) u64 swd[3][2 * OC_B * 12];

    const int tid = threadIdx.x;
    const int tx  = tid & 15;          // 16 threads across W (4 px each)
    const int ty  = tid >> 4;          // 8  threads across H (2 px each)
    const int w0  = blockIdx.x * 64;
    const int h0  = blockIdx.y * 16;
    const int b   = blockIdx.z / n_ocb;
    const int ocb = blockIdx.z % n_ocb;

    const int S = C_IN / 2;            // pipeline stages

    // input staging descriptors: 324 float4 per channel; 3 strided slots
    int goff[3]; bool val[3];
#pragma unroll
    for (int i = 0; i < 3; i++) {
        int idx = tid + i * 128;       // float4 index
        int r = idx / 18, q = idx - r * 18;
        int gh = h0 - 1 + r;
        int gws = w0 - 4 + q * 4;
        goff[i] = gh * WD + gws;
        val[i]  = (idx < 324) && ((unsigned)gh < 128u) &&
                  (gws >= 0) && (gws <= 124);
    }
    const unsigned sst = sm32(&st[0][0]);

    // weight staging: tid < 96 handles one (ch-in-stage, o, ky, kx[0..3]) slot
    bool wv = false; long wbase = 0; int s2_w = 0;
    if (tid < 2 * OC_B * 12) {
        s2_w   = tid / (OC_B * 12);
        int t  = tid - s2_w * (OC_B * 12);
        int o  = ocb * OC_B + t / 12;
        int ky = (t % 12) / 4;
        int kx = t % 4;
        wv     = (o < C_out) && (kx < 3);
        wbase  = (long)o * C_IN * 9 + ky * 3 + kx;
    }
    auto wld = [&](int s) -> float {
        int c = s * 2 + s2_w;
        return wv ? __ldg(wt + wbase + (long)c * 9) : 0.f;
    };

    auto planeof = [&](int c) -> const float* {
        if (CONCAT)
            return (c < 128) ? in0 + (size_t)(b * 128 + c) * HW
                             : in1 + (size_t)(b * 128 + (c - 128)) * HW;
        return in0 + (size_t)(b * C_IN + c) * HW;
    };

    auto issueIn = [&](int s, int slot) {
#pragma unroll
        for (int s2 = 0; s2 < 2; s2++) {
            const float* pl = planeof(s * 2 + s2);
            unsigned dst = sst + (slot * 2592 + s2 * 1296) * 4;
            cpa16(dst + (tid      ) * 16, pl + goff[0], val[0]);
            cpa16(dst + (tid + 128) * 16, pl + goff[1], val[1]);
            if (tid < 68)
                cpa16(dst + (tid + 256) * 16, pl + goff[2], val[2]);
        }
    };

    u64 acc[OC_B][2][2];
#pragma unroll
    for (int o = 0; o < OC_B; o++)
#pragma unroll
        for (int r = 0; r < 2; r++) { acc[o][r][0] = 0ull; acc[o][r][1] = 0ull; }

    // ---- prologue: stages 0,1 in flight; weights: stage0 in SMEM, stage1 in reg
    issueIn(0, 0); cpa_commit();
    issueIn(1, 1); cpa_commit();
    float wreg = 0.f;
    if (tid < 2 * OC_B * 12) {
        float t0 = wld(0);
        swd[0][tid] = pk(t0, t0);
        wreg = wld(1);
    }

    int slot = 0, nslot = 1;           // slot = s%3, nslot = (s+1)%3
#pragma unroll 1
    for (int s = 0; s < S; ++s) {
        cpa_wait<1>();                 // stage s input complete
        __syncthreads();               // publish stage s; readers of the slot
                                       // being refilled are done
        int wslot = (nslot == 2) ? 0 : nslot + 1;   // (s+2)%3
        if (s + 2 < S) issueIn(s + 2, wslot);
        cpa_commit();                  // uniform group count (may be empty)
        if (tid < 2 * OC_B * 12) {
            if (s + 1 < S) swd[nslot][tid] = pk(wreg, wreg);
            wreg = (s + 2 < S) ? wld(s + 2) : 0.f;
        }

        // ---- compute the 2 channels of stage s ----
        const float* sbuf = st[slot];
        const u64*   wbuf = swd[slot];
#pragma unroll
        for (int s2 = 0; s2 < 2; s2++) {
            const float* rowb = sbuf + s2 * 1296 + (ty * 2) * 72 + tx * 4;
            const u64*   wrow = wbuf + s2 * OC_B * 12;

            u64 P[2][5];
            auto loadrow = [&](int r, u64* Pd) {
                const float* rp = rowb + r * 72;
                float  l  = rp[3];
                float4 X  = *(const float4*)(rp + 4);
                float  rr = rp[8];
                Pd[0] = pk(l,   X.x);
                Pd[1] = pk(X.x, X.y);
                Pd[2] = pk(X.y, X.z);
                Pd[3] = pk(X.z, X.w);
                Pd[4] = pk(X.w, rr);
            };
            loadrow(0, P[0]);
            loadrow(1, P[1]);

#pragma unroll
            for (int ky = 0; ky < 3; ky++) {
                const u64* A = P[ky & 1];          // input row ky   (out row 0)
                const u64* B = P[(ky + 1) & 1];    // input row ky+1 (out row 1)
#pragma unroll
                for (int o = 0; o < OC_B; o++) {
                    ulonglong2 w01 = *(const ulonglong2*)(wrow + o * 12 + ky * 4);
                    u64        w2v = wrow[o * 12 + ky * 4 + 2];
                    acc[o][0][0] = fma2(A[0], w01.x, acc[o][0][0]);
                    acc[o][0][1] = fma2(A[2], w01.x, acc[o][0][1]);
                    acc[o][1][0] = fma2(B[0], w01.x, acc[o][1][0]);
                    acc[o][1][1] = fma2(B[2], w01.x, acc[o][1][1]);
                    acc[o][0][0] = fma2(A[1], w01.y, acc[o][0][0]);
                    acc[o][0][1] = fma2(A[3], w01.y, acc[o][0][1]);
                    acc[o][1][0] = fma2(B[1], w01.y, acc[o][1][0]);
                    acc[o][1][1] = fma2(B[3], w01.y, acc[o][1][1]);
                    acc[o][0][0] = fma2(A[2], w2v,   acc[o][0][0]);
                    acc[o][0][1] = fma2(A[4], w2v,   acc[o][0][1]);
                    acc[o][1][0] = fma2(B[2], w2v,   acc[o][1][0]);
                    acc[o][1][1] = fma2(B[4], w2v,   acc[o][1][1]);
                }
                if (ky < 2) loadrow(ky + 2, P[ky & 1]);   // roll window
            }
        }
        slot = nslot; nslot = wslot;
    }

    const int ph = h0 + ty * 2, pw = w0 + tx * 4;
#pragma unroll
    for (int o = 0; o < OC_B; o++) {
        int oc = ocb * OC_B + o;
        if (oc >= C_out) break;
        float* op = out + (size_t)(b * C_out + oc) * HW + ph * WD + pw;
#pragma unroll
        for (int r = 0; r < 2; r++) {
            float4 v;
            upk(acc[o][r][0], v.x, v.y);
            upk(acc[o][r][1], v.z, v.w);
            if (RELU) {
                v.x = fmaxf(v.x, 0.f); v.y = fmaxf(v.y, 0.f);
                v.z = fmaxf(v.z, 0.f); v.w = fmaxf(v.w, 0.f);
            }
            *(float4*)(op + r * WD) = v;
        }
    }
}

// ---------------------------------------------------------------------------
__global__ void transpose_wdef(const float* __restrict__ w, float* __restrict__ wtp)
{
    int idx = blockIdx.x * 256 + threadIdx.x;
    if (idx >= 9 * 128 * 128) return;
    int o = idx & 127;
    int c = (idx >> 7) & 127;
    int k = idx >> 14;
    wtp[idx] = w[((size_t)o * 128 + c) * 9 + k];
}

__global__ void dummy_k(float* p) { p[threadIdx.x] = 0.f; }

// ---------------------------------------------------------------------------
// Fused deformable conv v4 (unchanged from round 5): 256 threads, 128 pixels,
// all 128 output channels. Double-buffered SMEM, one barrier per iteration,
// 36 iterations = 9 taps x 4 chunks of 32 channels, gather/compute pipelined.
// ---------------------------------------------------------------------------
__global__ __launch_bounds__(256, 2) void deform_k(
    const float* __restrict__ ref, const float* __restrict__ off,
    const float* __restrict__ wtp, float* __restrict__ out)
{
    extern __shared__ __align__(16) float dsm[];
    float* s_s = dsm;           // [2][32*128] sampled values [c][px]
    float* s_w = dsm + 8192;    // [2][32*128] weights        [c][oc]

    const int tid  = threadIdx.x;
    const int pxg  = tid & 127;          // gather pixel
    const int ch16 = (tid >> 7) * 16;    // gather channel sub-block
    const int wg = blockIdx.x * 16 + (pxg & 15);
    const int hg = blockIdx.y * 8  + (pxg >> 4);
    const int b  = blockIdx.z;

    const int pxc = (tid & 63) * 2;      // compute pixel pair base
    const int q   = tid >> 6;            // oc quarter (0..3)
    const int wc = blockIdx.x * 16 + (pxc & 15);
    const int hc = blockIdx.y * 8  + (pxc >> 4);

    u64 a2[2][16];
#pragma unroll
    for (int p = 0; p < 2; p++)
#pragma unroll
        for (int j = 0; j < 16; j++) a2[p][j] = 0ull;

    const float* offp = off + (size_t)b * 18 * HW + hg * WD + wg;
    const float* pb   = ref + (size_t)b * 128 * HW;

    float  sv[16];
    float4 wv4[4];

    auto gather = [&](int it) {
        const int k = it >> 2, chunk = it & 3;
        float dy = __ldg(offp + (2 * k)     * HW);
        float dx = __ldg(offp + (2 * k + 1) * HW);
        float py = (float)(hg + (k / 3) - 1) + dy;
        float px = (float)(wg + (k % 3) - 1) + dx;
        float y0f = floorf(py), x0f = floorf(px);
        float wy = py - y0f, wx = px - x0f;
        int y0 = (int)y0f, x0 = (int)x0f;
        int y1 = y0 + 1,   x1 = x0 + 1;
        bool vy0 = (unsigned)y0 < 128u, vy1 = (unsigned)y1 < 128u;
        bool vx0 = (unsigned)x0 < 128u, vx1 = (unsigned)x1 < 128u;
        int y0c = min(max(y0, 0), 127), y1c = min(max(y1, 0), 127);
        int x0c = min(max(x0, 0), 127), x1c = min(max(x1, 0), 127);
        float w00 = (1.f - wy) * (1.f - wx) * ((vy0 && vx0) ? 1.f : 0.f);
        float w01 = (1.f - wy) * wx         * ((vy0 && vx1) ? 1.f : 0.f);
        float w10 = wy * (1.f - wx)         * ((vy1 && vx0) ? 1.f : 0.f);
        float w11 = wy * wx                 * ((vy1 && vx1) ? 1.f : 0.f);
        int o00 = y0c * WD + x0c, o01 = y0c * WD + x1c;
        int o10 = y1c * WD + x0c, o11 = y1c * WD + x1c;

        const float* plb = pb + (size_t)(chunk * 32 + ch16) * HW;
#pragma unroll
        for (int i = 0; i < 16; i++) {
            const float* pl = plb + (size_t)i * HW;
            sv[i] = w00 * __ldg(pl + o00) + w01 * __ldg(pl + o01)
                  + w10 * __ldg(pl + o10) + w11 * __ldg(pl + o11);
        }
        const float4* wsrc = (const float4*)(wtp + (size_t)k * 16384 + chunk * 32 * 128);
#pragma unroll
        for (int j = 0; j < 4; j++) wv4[j] = __ldg(wsrc + tid + j * 256);
    };

    gather(0);

#pragma unroll 1
    for (int it = 0; it < 36; ++it) {
        const int buf = it & 1;
        float* ss = s_s + buf * 4096;
        float* sw = s_w + buf * 4096;
#pragma unroll
        for (int i = 0; i < 16; i++) ss[(ch16 + i) * 128 + pxg] = sv[i];
        {
            float4* wd4 = (float4*)sw;
#pragma unroll
            for (int j = 0; j < 4; j++) wd4[tid + j * 256] = wv4[j];
        }
        __syncthreads();

        if (it + 1 < 36) gather(it + 1);   // LDG latency hidden by compute

#pragma unroll 4
        for (int c = 0; c < 32; ++c) {
            float2 s2v = *(const float2*)(ss + c * 128 + pxc);
            u64 ss0 = pk(s2v.x, s2v.x);
            u64 ss1 = pk(s2v.y, s2v.y);
            const ulonglong2* wr = (const ulonglong2*)(sw + c * 128 + q * 32);
#pragma unroll
            for (int j = 0; j < 8; j++) {
                ulonglong2 w2 = wr[j];
                a2[0][2 * j]     = fma2(w2.x, ss0, a2[0][2 * j]);
                a2[0][2 * j + 1] = fma2(w2.y, ss0, a2[0][2 * j + 1]);
                a2[1][2 * j]     = fma2(w2.x, ss1, a2[1][2 * j]);
                a2[1][2 * j + 1] = fma2(w2.y, ss1, a2[1][2 * j + 1]);
            }
        }
    }

    float* ob = out + (size_t)(b * 128 + q * 32) * HW + hc * WD + wc;
#pragma unroll
    for (int j = 0; j < 16; j++) {
        float v0, v1, u0, u1;
        upk(a2[0][j], v0, v1);
        upk(a2[1][j], u0, u1);
        float2 e; e.x = v0; e.y = u0;
        float2 f; f.x = v1; f.y = u1;
        *(float2*)(ob + (size_t)(2 * j)     * HW) = e;
        *(float2*)(ob + (size_t)(2 * j + 1) * HW) = f;
    }
}

// ---------------------------------------------------------------------------
extern "C" void kernel_launch(void* const* d_in, const int* in_sizes, int n_in,
                              void* d_out, int out_size)
{
    const float* x  = (const float*)d_in[0];  // input_features
    const float* rf = (const float*)d_in[1];  // reference_features
    const float* w1 = (const float*)d_in[2];  // w_est1 [128,256,3,3]
    const float* w2 = (const float*)d_in[3];  // w_est2 [128,128,3,3]
    const float* wo = (const float*)d_in[4];  // w_off  [18,128,3,3]
    const float* wd = (const float*)d_in[5];  // w_def  [128,128,3,3]
    float* out = (float*)d_out;

    const int B = in_sizes[0] / (128 * HW);   // 2

    float *e1, *e2, *of, *wtp, *dmy;
    cudaGetSymbolAddress((void**)&e1,  g_est1);
    cudaGetSymbolAddress((void**)&e2,  g_est2);
    cudaGetSymbolAddress((void**)&of,  g_off);
    cudaGetSymbolAddress((void**)&wtp, g_wt);
    cudaGetSymbolAddress((void**)&dmy, g_dmy);

    cudaFuncSetAttribute(deform_k,
        cudaFuncAttributeMaxDynamicSharedMemorySize, 65536);

    dim3 blk(128);

    // launches 1-3 (dummies + transpose) keep conv1 in the profiled slot
    dummy_k<<<1, 128>>>(dmy);
    dummy_k<<<1, 128>>>(dmy);
    transpose_wdef<<<(9 * 128 * 128 + 255) / 256, 256>>>(wd, wtp);
    // est = relu(conv(concat(x, rf), w_est1))
    conv3x3_k<256, 4, true,  true ><<<dim3(2, 8, B * 32), blk>>>(x,  rf,      w1, e1, 128, 32);
    // est = relu(conv(est, w_est2))
    conv3x3_k<128, 4, true,  false><<<dim3(2, 8, B * 32), blk>>>(e1, nullptr, w2, e2, 128, 32);
    // offset = conv(est, w_off)
    conv3x3_k<128, 4, false, false><<<dim3(2, 8, B * 5),  blk>>>(e2, nullptr, wo, of, 18,  5);
    // out = deform_conv2d(rf, offset, w_def)
    deform_k<<<dim3(8, 16, B), 256, 65536>>>(rf, of, wtp, out);
}

// round 7
// speedup vs baseline: 1.0193x; 1.0193x over previous
#include <cuda_runtime.h>

#define HW 16384
#define WD 128

typedef unsigned long long u64;

// Scratch (allocation-free rule: __device__ globals)
__device__ float g_est1[2 * 128 * HW];   // 16 MB
__device__ float g_est2[2 * 128 * HW];   // 16 MB
__device__ float g_off [2 * 18  * HW];   // 2.25 MB
__device__ float g_wt  [9 * 128 * 128];  // w_def transposed to [k][c][o]
__device__ float g_dmy [128];

// ---- packed fp32x2 helpers -------------------------------------------------
__device__ __forceinline__ u64 pk(float lo, float hi) {
    u64 r; asm("mov.b64 %0, {%1, %2};" : "=l"(r) : "f"(lo), "f"(hi)); return r;
}
__device__ __forceinline__ void upk(u64 v, float& lo, float& hi) {
    asm("mov.b64 {%0, %1}, %2;" : "=f"(lo), "=f"(hi) : "l"(v));
}
__device__ __forceinline__ u64 fma2(u64 a, u64 b, u64 c) {
    u64 d; asm("fma.rn.f32x2 %0, %1, %2, %3;" : "=l"(d) : "l"(a), "l"(b), "l"(c));
    return d;
}

// ---- TMA-1D bulk + mbarrier helpers -----------------------------------------
__device__ __forceinline__ unsigned sm32(const void* p) {
    return (unsigned)__cvta_generic_to_shared(p);
}
__device__ __forceinline__ void mbar_init(unsigned mbar, unsigned cnt) {
    asm volatile("mbarrier.init.shared.b64 [%0], %1;" :: "r"(mbar), "r"(cnt) : "memory");
}
__device__ __forceinline__ void mbar_expect(unsigned mbar, unsigned bytes) {
    asm volatile("mbarrier.arrive.expect_tx.shared.b64 _, [%0], %1;"
                 :: "r"(mbar), "r"(bytes) : "memory");
}
__device__ __forceinline__ void bulk_g2s(unsigned dst, const void* src,
                                         unsigned bytes, unsigned mbar) {
    asm volatile(
        "cp.async.bulk.shared::cluster.global.mbarrier::complete_tx::bytes "
        "[%0], [%1], %2, [%3];"
        :: "r"(dst), "l"(src), "r"(bytes), "r"(mbar) : "memory");
}
__device__ __forceinline__ void mbar_wait(unsigned mbar, unsigned parity) {
    asm volatile(
        "{\n\t"
        ".reg .pred P;\n"
        "WAIT_%=:\n\t"
        "mbarrier.try_wait.parity.shared.b64 P, [%0], %1;\n\t"
        "@!P bra WAIT_%=;\n\t"
        "}"
        :: "r"(mbar), "r"(parity) : "memory");
}

// ---------------------------------------------------------------------------
// Direct 3x3 conv, stride 1, pad 1, NCHW, H=W=128, fp32x2 math.
// Staging: ONE cp.async.bulk (TMA-1D) per channel — the 18-row halo band is
// contiguous in global (full 128-float rows). 3-slot ring, distance 2,
// mbarrier completion, one __syncthreads per channel. Boundary rows (gh=-1 /
// gh=128) zero-filled by STS each refill.
// Block: 128 threads; output tile 16(h) x 64(w); thread: 2 rows x 4 cols;
// OC_B output channels register-blocked.
// ---------------------------------------------------------------------------
template <int C_IN, int OC_B, bool RELU, bool CONCAT>
__global__ __launch_bounds__(128, 4) void conv3x3_k(
    const float* __restrict__ in0, const float* __restrict__ in1,
    const float* __restrict__ wt, float* __restrict__ out,
    int C_out, int n_ocb)
{
    __shared__ __align__(16) float st[3][18 * 128];       // 3 x 9216 B
    __shared__ __align__(16) u64   swd[3][OC_B * 12];
    __shared__ __align__(8)  u64   mbar[3];

    const int tid = threadIdx.x;
    const int tx  = tid & 15;          // 16 threads across W (4 px each)
    const int ty  = tid >> 4;          // 8  threads across H (2 px each)
    const int w0  = blockIdx.x * 64;
    const int h0  = blockIdx.y * 16;
    const int b   = blockIdx.z / n_ocb;
    const int ocb = blockIdx.z % n_ocb;

    const bool topB = (h0 == 0);
    const bool botB = (h0 == 112);
    const int  row0   = topB ? 1 : 0;              // first SMEM row TMA writes
    const int  nrows  = 18 - (int)topB - (int)botB;
    const unsigned nbytes = nrows * 512;
    const int  gh0    = topB ? 0 : (h0 - 1);       // first global row

    const int cq = w0 + tx * 4;                    // this thread's first out col
    const bool eL = (cq == 0);
    const bool eR = (cq == 124);

    // weight staging: tid < OC_B*12 handles one (o, ky, kx[0..3]) slot
    bool wv = false; long wbase = 0;
    if (tid < OC_B * 12) {
        int o  = ocb * OC_B + tid / 12;
        int ky = (tid % 12) / 4;
        int kx = tid % 4;
        wv     = (o < C_out) && (kx < 3);
        wbase  = (long)o * C_IN * 9 + ky * 3 + kx;
    }
    auto wld = [&](int c) -> float {
        return wv ? __ldg(wt + wbase + (long)c * 9) : 0.f;
    };

    auto planeof = [&](int c) -> const float* {
        if (CONCAT)
            return (c < 128) ? in0 + (size_t)(b * 128 + c) * HW
                             : in1 + (size_t)(b * 128 + (c - 128)) * HW;
        return in0 + (size_t)(b * C_IN + c) * HW;
    };

    // refill slot with channel c: tid0 issues TMA; all threads zero halo rows
    auto issue = [&](int c, int slot) {
        if (tid == 0) {
            unsigned mb = sm32(&mbar[slot]);
            mbar_expect(mb, nbytes);
            bulk_g2s(sm32(&st[slot][row0 * 128]),
                     planeof(c) + gh0 * WD, nbytes, mb);
        }
        if (topB) st[slot][tid] = 0.f;
        if (botB) st[slot][17 * 128 + tid] = 0.f;
    };

    u64 acc[OC_B][2][2];
#pragma unroll
    for (int o = 0; o < OC_B; o++)
#pragma unroll
        for (int r = 0; r < 2; r++) { acc[o][r][0] = 0ull; acc[o][r][1] = 0ull; }

    // ---- prologue ----
    if (tid == 0) {
#pragma unroll
        for (int j = 0; j < 3; j++) mbar_init(sm32(&mbar[j]), 1);
    }
    __syncthreads();                   // mbarriers visible before TMA targets them

    issue(0, 0);
    issue(1, 1);
    float wreg;                        // weight for channel s+1 at iter s
    {
        float t0 = wld(0);
        if (tid < OC_B * 12) swd[0][tid] = pk(t0, t0);
        wreg = wld(1);
    }
    __syncthreads();                   // swd[0] + zero rows published

#pragma unroll 1
    for (int s = 0; s < C_IN; ++s) {
        const int slot = s % 3;
        mbar_wait(sm32(&mbar[slot]), (unsigned)((s / 3) & 1));

        // ---- compute channel s ----
        const float* sbuf = st[slot];
        const u64*   wrow = swd[slot];
        {
            u64 P[2][5];
            auto loadrow = [&](int r, u64* Pd) {
                const float* base = sbuf + r * 128;
                float  l  = eL ? 0.f : base[cq - 1];
                float4 X  = *(const float4*)(base + cq);
                float  rr = eR ? 0.f : base[cq + 4];
                Pd[0] = pk(l,   X.x);
                Pd[1] = pk(X.x, X.y);
                Pd[2] = pk(X.y, X.z);
                Pd[3] = pk(X.z, X.w);
                Pd[4] = pk(X.w, rr);
            };
            const int r0 = ty * 2;     // rows r0..r0+3 of the 18-row band
            loadrow(r0,     P[0]);
            loadrow(r0 + 1, P[1]);
#pragma unroll
            for (int ky = 0; ky < 3; ky++) {
                const u64* A = P[ky & 1];
                const u64* B = P[(ky + 1) & 1];
#pragma unroll
                for (int o = 0; o < OC_B; o++) {
                    ulonglong2 w01 = *(const ulonglong2*)(wrow + o * 12 + ky * 4);
                    u64        w2v = wrow[o * 12 + ky * 4 + 2];
                    acc[o][0][0] = fma2(A[0], w01.x, acc[o][0][0]);
                    acc[o][0][1] = fma2(A[2], w01.x, acc[o][0][1]);
                    acc[o][1][0] = fma2(B[0], w01.x, acc[o][1][0]);
                    acc[o][1][1] = fma2(B[2], w01.x, acc[o][1][1]);
                    acc[o][0][0] = fma2(A[1], w01.y, acc[o][0][0]);
                    acc[o][0][1] = fma2(A[3], w01.y, acc[o][0][1]);
                    acc[o][1][0] = fma2(B[1], w01.y, acc[o][1][0]);
                    acc[o][1][1] = fma2(B[3], w01.y, acc[o][1][1]);
                    acc[o][0][0] = fma2(A[2], w2v,   acc[o][0][0]);
                    acc[o][0][1] = fma2(A[4], w2v,   acc[o][0][1]);
                    acc[o][1][0] = fma2(B[2], w2v,   acc[o][1][0]);
                    acc[o][1][1] = fma2(B[4], w2v,   acc[o][1][1]);
                }
                if (ky < 2) loadrow(r0 + ky + 2, P[ky & 1]);
            }
        }

        // ---- stage weights for channel s+1 (read after the sync below) ----
        if (s + 1 < C_IN) {
            if (tid < OC_B * 12) swd[(s + 1) % 3][tid] = pk(wreg, wreg);
            wreg = (s + 2 < C_IN) ? wld(s + 2) : 0.f;
        }
        __syncthreads();               // all reads of slot (s+2)%3 (=iter s-1)
                                       // done; swd[s+1] published
        if (s + 2 < C_IN) issue(s + 2, (s + 2) % 3);
    }

    const int ph = h0 + ty * 2, pw = w0 + tx * 4;
#pragma unroll
    for (int o = 0; o < OC_B; o++) {
        int oc = ocb * OC_B + o;
        if (oc >= C_out) break;
        float* op = out + (size_t)(b * C_out + oc) * HW + ph * WD + pw;
#pragma unroll
        for (int r = 0; r < 2; r++) {
            float4 v;
            upk(acc[o][r][0], v.x, v.y);
            upk(acc[o][r][1], v.z, v.w);
            if (RELU) {
                v.x = fmaxf(v.x, 0.f); v.y = fmaxf(v.y, 0.f);
                v.z = fmaxf(v.z, 0.f); v.w = fmaxf(v.w, 0.f);
            }
            *(float4*)(op + r * WD) = v;
        }
    }
}

// ---------------------------------------------------------------------------
__global__ void transpose_wdef(const float* __restrict__ w, float* __restrict__ wtp)
{
    int idx = blockIdx.x * 256 + threadIdx.x;
    if (idx >= 9 * 128 * 128) return;
    int o = idx & 127;
    int c = (idx >> 7) & 127;
    int k = idx >> 14;
    wtp[idx] = w[((size_t)o * 128 + c) * 9 + k];
}

__global__ void dummy_k(float* p) { p[threadIdx.x] = 0.f; }

// ---------------------------------------------------------------------------
// Fused deformable conv (unchanged from round 5 passing version).
// ---------------------------------------------------------------------------
__global__ __launch_bounds__(256, 2) void deform_k(
    const float* __restrict__ ref, const float* __restrict__ off,
    const float* __restrict__ wtp, float* __restrict__ out)
{
    extern __shared__ __align__(16) float dsm[];
    float* s_s = dsm;           // [2][32*128] sampled values [c][px]
    float* s_w = dsm + 8192;    // [2][32*128] weights        [c][oc]

    const int tid  = threadIdx.x;
    const int pxg  = tid & 127;
    const int ch16 = (tid >> 7) * 16;
    const int wg = blockIdx.x * 16 + (pxg & 15);
    const int hg = blockIdx.y * 8  + (pxg >> 4);
    const int b  = blockIdx.z;

    const int pxc = (tid & 63) * 2;
    const int q   = tid >> 6;
    const int wc = blockIdx.x * 16 + (pxc & 15);
    const int hc = blockIdx.y * 8  + (pxc >> 4);

    u64 a2[2][16];
#pragma unroll
    for (int p = 0; p < 2; p++)
#pragma unroll
        for (int j = 0; j < 16; j++) a2[p][j] = 0ull;

    const float* offp = off + (size_t)b * 18 * HW + hg * WD + wg;
    const float* pb   = ref + (size_t)b * 128 * HW;

    float  sv[16];
    float4 wv4[4];

    auto gather = [&](int it) {
        const int k = it >> 2, chunk = it & 3;
        float dy = __ldg(offp + (2 * k)     * HW);
        float dx = __ldg(offp + (2 * k + 1) * HW);
        float py = (float)(hg + (k / 3) - 1) + dy;
        float px = (float)(wg + (k % 3) - 1) + dx;
        float y0f = floorf(py), x0f = floorf(px);
        float wy = py - y0f, wx = px - x0f;
        int y0 = (int)y0f, x0 = (int)x0f;
        int y1 = y0 + 1,   x1 = x0 + 1;
        bool vy0 = (unsigned)y0 < 128u, vy1 = (unsigned)y1 < 128u;
        bool vx0 = (unsigned)x0 < 128u, vx1 = (unsigned)x1 < 128u;
        int y0c = min(max(y0, 0), 127), y1c = min(max(y1, 0), 127);
        int x0c = min(max(x0, 0), 127), x1c = min(max(x1, 0), 127);
        float w00 = (1.f - wy) * (1.f - wx) * ((vy0 && vx0) ? 1.f : 0.f);
        float w01 = (1.f - wy) * wx         * ((vy0 && vx1) ? 1.f : 0.f);
        float w10 = wy * (1.f - wx)         * ((vy1 && vx0) ? 1.f : 0.f);
        float w11 = wy * wx                 * ((vy1 && vx1) ? 1.f : 0.f);
        int o00 = y0c * WD + x0c, o01 = y0c * WD + x1c;
        int o10 = y1c * WD + x0c, o11 = y1c * WD + x1c;

        const float* plb = pb + (size_t)(chunk * 32 + ch16) * HW;
#pragma unroll
        for (int i = 0; i < 16; i++) {
            const float* pl = plb + (size_t)i * HW;
            sv[i] = w00 * __ldg(pl + o00) + w01 * __ldg(pl + o01)
                  + w10 * __ldg(pl + o10) + w11 * __ldg(pl + o11);
        }
        const float4* wsrc = (const float4*)(wtp + (size_t)k * 16384 + chunk * 32 * 128);
#pragma unroll
        for (int j = 0; j < 4; j++) wv4[j] = __ldg(wsrc + tid + j * 256);
    };

    gather(0);

#pragma unroll 1
    for (int it = 0; it < 36; ++it) {
        const int buf = it & 1;
        float* ss = s_s + buf * 4096;
        float* sw = s_w + buf * 4096;
#pragma unroll
        for (int i = 0; i < 16; i++) ss[(ch16 + i) * 128 + pxg] = sv[i];
        {
            float4* wd4 = (float4*)sw;
#pragma unroll
            for (int j = 0; j < 4; j++) wd4[tid + j * 256] = wv4[j];
        }
        __syncthreads();

        if (it + 1 < 36) gather(it + 1);

#pragma unroll 4
        for (int c = 0; c < 32; ++c) {
            float2 s2v = *(const float2*)(ss + c * 128 + pxc);
            u64 ss0 = pk(s2v.x, s2v.x);
            u64 ss1 = pk(s2v.y, s2v.y);
            const ulonglong2* wr = (const ulonglong2*)(sw + c * 128 + q * 32);
#pragma unroll
            for (int j = 0; j < 8; j++) {
                ulonglong2 w2 = wr[j];
                a2[0][2 * j]     = fma2(w2.x, ss0, a2[0][2 * j]);
                a2[0][2 * j + 1] = fma2(w2.y, ss0, a2[0][2 * j + 1]);
                a2[1][2 * j]     = fma2(w2.x, ss1, a2[1][2 * j]);
                a2[1][2 * j + 1] = fma2(w2.y, ss1, a2[1][2 * j + 1]);
            }
        }
    }

    float* ob = out + (size_t)(b * 128 + q * 32) * HW + hc * WD + wc;
#pragma unroll
    for (int j = 0; j < 16; j++) {
        float v0, v1, u0, u1;
        upk(a2[0][j], v0, v1);
        upk(a2[1][j], u0, u1);
        float2 e; e.x = v0; e.y = u0;
        float2 f; f.x = v1; f.y = u1;
        *(float2*)(ob + (size_t)(2 * j)     * HW) = e;
        *(float2*)(ob + (size_t)(2 * j + 1) * HW) = f;
    }
}

// ---------------------------------------------------------------------------
extern "C" void kernel_launch(void* const* d_in, const int* in_sizes, int n_in,
                              void* d_out, int out_size)
{
    const float* x  = (const float*)d_in[0];  // input_features
    const float* rf = (const float*)d_in[1];  // reference_features
    const float* w1 = (const float*)d_in[2];  // w_est1 [128,256,3,3]
    const float* w2 = (const float*)d_in[3];  // w_est2 [128,128,3,3]
    const float* wo = (const float*)d_in[4];  // w_off  [18,128,3,3]
    const float* wd = (const float*)d_in[5];  // w_def  [128,128,3,3]
    float* out = (float*)d_out;

    const int B = in_sizes[0] / (128 * HW);   // 2

    float *e1, *e2, *of, *wtp, *dmy;
    cudaGetSymbolAddress((void**)&e1,  g_est1);
    cudaGetSymbolAddress((void**)&e2,  g_est2);
    cudaGetSymbolAddress((void**)&of,  g_off);
    cudaGetSymbolAddress((void**)&wtp, g_wt);
    cudaGetSymbolAddress((void**)&dmy, g_dmy);

    cudaFuncSetAttribute(deform_k,
        cudaFuncAttributeMaxDynamicSharedMemorySize, 65536);

    dim3 blk(128);

    // launches 1-3 (dummies + transpose) keep conv1 in the profiled slot
    dummy_k<<<1, 128>>>(dmy);
    dummy_k<<<1, 128>>>(dmy);
    transpose_wdef<<<(9 * 128 * 128 + 255) / 256, 256>>>(wd, wtp);
    // est = relu(conv(concat(x, rf), w_est1)) : OC_B=8, 16 oc-blocks
    conv3x3_k<256, 8, true,  true ><<<dim3(2, 8, B * 16), blk>>>(x,  rf,      w1, e1, 128, 16);
    // est = relu(conv(est, w_est2))
    conv3x3_k<128, 8, true,  false><<<dim3(2, 8, B * 16), blk>>>(e1, nullptr, w2, e2, 128, 16);
    // offset = conv(est, w_off) : OC_B=6, 3 oc-blocks
    conv3x3_k<128, 6, false, false><<<dim3(2, 8, B * 3),  blk>>>(e2, nullptr, wo, of, 18,  3);
    // out = deform_conv2d(rf, offset, w_def)
    deform_k<<<dim3(8, 16, B), 256, 65536>>>(rf, of, wtp, out);
}

// round 8
// speedup vs baseline: 1.0252x; 1.0058x over previous
#include <cuda_runtime.h>

#define HW 16384
#define WD 128

typedef unsigned long long u64;

// Scratch (allocation-free rule: __device__ globals)
__device__ float g_est1[2 * 128 * HW];   // 16 MB
__device__ float g_est2[2 * 128 * HW];   // 16 MB
__device__ float g_off [2 * 18  * HW];   // 2.25 MB
__device__ float g_wt  [9 * 128 * 128];  // w_def transposed to [k][c][o]
__device__ float g_dmy [128];

// ---- packed fp32x2 helpers -------------------------------------------------
__device__ __forceinline__ u64 pk(float lo, float hi) {
    u64 r; asm("mov.b64 %0, {%1, %2};" : "=l"(r) : "f"(lo), "f"(hi)); return r;
}
__device__ __forceinline__ void upk(u64 v, float& lo, float& hi) {
    asm("mov.b64 {%0, %1}, %2;" : "=f"(lo), "=f"(hi) : "l"(v));
}
__device__ __forceinline__ u64 fma2(u64 a, u64 b, u64 c) {
    u64 d; asm("fma.rn.f32x2 %0, %1, %2, %3;" : "=l"(d) : "l"(a), "l"(b), "l"(c));
    return d;
}

// ---- TMA-1D bulk + mbarrier helpers -----------------------------------------
__device__ __forceinline__ unsigned sm32(const void* p) {
    return (unsigned)__cvta_generic_to_shared(p);
}
__device__ __forceinline__ void mbar_init(unsigned mbar, unsigned cnt) {
    asm volatile("mbarrier.init.shared.b64 [%0], %1;" :: "r"(mbar), "r"(cnt) : "memory");
}
__device__ __forceinline__ void mbar_expect(unsigned mbar, unsigned bytes) {
    asm volatile("mbarrier.arrive.expect_tx.shared.b64 _, [%0], %1;"
                 :: "r"(mbar), "r"(bytes) : "memory");
}
__device__ __forceinline__ void bulk_g2s(unsigned dst, const void* src,
                                         unsigned bytes, unsigned mbar) {
    asm volatile(
        "cp.async.bulk.shared::cluster.global.mbarrier::complete_tx::bytes "
        "[%0], [%1], %2, [%3];"
        :: "r"(dst), "l"(src), "r"(bytes), "r"(mbar) : "memory");
}
__device__ __forceinline__ void mbar_wait(unsigned mbar, unsigned parity) {
    asm volatile(
        "{\n\t"
        ".reg .pred P;\n"
        "WAIT_%=:\n\t"
        "mbarrier.try_wait.parity.shared.b64 P, [%0], %1;\n\t"
        "@!P bra WAIT_%=;\n\t"
        "}"
        :: "r"(mbar), "r"(parity) : "memory");
}

// ---------------------------------------------------------------------------
// Direct 3x3 conv, stride 1, pad 1, NCHW, H=W=128, fp32x2 math.
// SMALL TILE FOR OCCUPANCY: 8(h) x 64(w), thread = 1 row x 4 cols, OC_B
// output channels register-blocked (acc = OC_B*2 u64 = 32 regs @ OC_B=8).
// Staging: ONE cp.async.bulk (TMA-1D) per channel (10 full-width rows,
// 5120 B). 3-slot ring, distance 2, mbarrier completion, one __syncthreads
// per channel. Boundary rows zero-filled by STS on refill.
// ---------------------------------------------------------------------------
template <int C_IN, int OC_B, bool RELU, bool CONCAT>
__global__ __launch_bounds__(128, 6) void conv3x3_k(
    const float* __restrict__ in0, const float* __restrict__ in1,
    const float* __restrict__ wt, float* __restrict__ out,
    int C_out, int n_ocb)
{
    __shared__ __align__(16) float st[3][10 * 128];       // 3 x 5120 B
    __shared__ __align__(16) u64   swd[3][OC_B * 12];
    __shared__ __align__(8)  u64   mbar[3];

    const int tid = threadIdx.x;
    const int tx  = tid & 15;          // 16 threads across W (4 px each)
    const int ty  = tid >> 4;          // 8 rows, 1 row each
    const int w0  = blockIdx.x * 64;
    const int h0  = blockIdx.y * 8;
    const int b   = blockIdx.z / n_ocb;
    const int ocb = blockIdx.z % n_ocb;

    const bool topB = (h0 == 0);
    const bool botB = (h0 == 120);
    const int  row0   = topB ? 1 : 0;              // first SMEM row TMA writes
    const int  nrows  = 10 - (int)topB - (int)botB;
    const unsigned nbytes = nrows * 512;
    const int  gh0    = topB ? 0 : (h0 - 1);       // first global row

    const int cq = w0 + tx * 4;                    // first out col of thread
    const bool eL = (cq == 0);
    const bool eR = (cq == 124);

    // weight staging: tid < OC_B*12 handles one (o, ky, kx[0..3]) slot
    bool wv = false; long wbase = 0;
    if (tid < OC_B * 12) {
        int o  = ocb * OC_B + tid / 12;
        int ky = (tid % 12) / 4;
        int kx = tid % 4;
        wv     = (o < C_out) && (kx < 3);
        wbase  = (long)o * C_IN * 9 + ky * 3 + kx;
    }
    auto wld = [&](int c) -> float {
        return wv ? __ldg(wt + wbase + (long)c * 9) : 0.f;
    };

    auto planeof = [&](int c) -> const float* {
        if (CONCAT)
            return (c < 128) ? in0 + (size_t)(b * 128 + c) * HW
                             : in1 + (size_t)(b * 128 + (c - 128)) * HW;
        return in0 + (size_t)(b * C_IN + c) * HW;
    };

    // refill slot with channel c: tid0 issues TMA; zero halo rows by STS
    auto issue = [&](int c, int slot) {
        if (tid == 0) {
            unsigned mb = sm32(&mbar[slot]);
            mbar_expect(mb, nbytes);
            bulk_g2s(sm32(&st[slot][row0 * 128]),
                     planeof(c) + gh0 * WD, nbytes, mb);
        }
        if (topB) st[slot][tid] = 0.f;
        if (botB) st[slot][9 * 128 + tid] = 0.f;
    };

    u64 acc[OC_B][2];
#pragma unroll
    for (int o = 0; o < OC_B; o++) { acc[o][0] = 0ull; acc[o][1] = 0ull; }

    // ---- prologue ----
    if (tid == 0) {
#pragma unroll
        for (int j = 0; j < 3; j++) mbar_init(sm32(&mbar[j]), 1);
    }
    __syncthreads();                   // mbarriers visible before TMA

    issue(0, 0);
    issue(1, 1);
    float wreg;                        // weight for channel s+1 at iter s
    {
        float t0 = wld(0);
        if (tid < OC_B * 12) swd[0][tid] = pk(t0, t0);
        wreg = wld(1);
    }
    __syncthreads();                   // swd[0] + zero rows published

#pragma unroll 1
    for (int s = 0; s < C_IN; ++s) {
        const int slot = s % 3;
        mbar_wait(sm32(&mbar[slot]), (unsigned)((s / 3) & 1));

        // ---- compute channel s: out row h0+ty needs band rows ty..ty+2 ----
        const float* sbuf = st[slot];
        const u64*   wrow = swd[slot];
#pragma unroll
        for (int ky = 0; ky < 3; ky++) {
            const float* base = sbuf + (ty + ky) * 128;
            float  l  = eL ? 0.f : base[cq - 1];
            float4 X  = *(const float4*)(base + cq);
            float  rr = eR ? 0.f : base[cq + 4];
            u64 P0 = pk(l,   X.x);
            u64 P1 = pk(X.x, X.y);
            u64 P2 = pk(X.y, X.z);
            u64 P3 = pk(X.z, X.w);
            u64 P4 = pk(X.w, rr);
#pragma unroll
            for (int o = 0; o < OC_B; o++) {
                ulonglong2 w01 = *(const ulonglong2*)(wrow + o * 12 + ky * 4);
                u64        w2v = wrow[o * 12 + ky * 4 + 2];
                acc[o][0] = fma2(P0, w01.x, acc[o][0]);
                acc[o][1] = fma2(P2, w01.x, acc[o][1]);
                acc[o][0] = fma2(P1, w01.y, acc[o][0]);
                acc[o][1] = fma2(P3, w01.y, acc[o][1]);
                acc[o][0] = fma2(P2, w2v,   acc[o][0]);
                acc[o][1] = fma2(P4, w2v,   acc[o][1]);
            }
        }

        // ---- stage weights for channel s+1 (read after the sync below) ----
        if (s + 1 < C_IN) {
            if (tid < OC_B * 12) swd[(s + 1) % 3][tid] = pk(wreg, wreg);
            wreg = (s + 2 < C_IN) ? wld(s + 2) : 0.f;
        }
        __syncthreads();               // readers of slot (s+2)%3 done;
                                       // swd[s+1] published
        if (s + 2 < C_IN) issue(s + 2, (s + 2) % 3);
    }

    const int ph = h0 + ty;
#pragma unroll
    for (int o = 0; o < OC_B; o++) {
        int oc = ocb * OC_B + o;
        if (oc >= C_out) break;
        float* op = out + (size_t)(b * C_out + oc) * HW + ph * WD + cq;
        float4 v;
        upk(acc[o][0], v.x, v.y);
        upk(acc[o][1], v.z, v.w);
        if (RELU) {
            v.x = fmaxf(v.x, 0.f); v.y = fmaxf(v.y, 0.f);
            v.z = fmaxf(v.z, 0.f); v.w = fmaxf(v.w, 0.f);
        }
        *(float4*)op = v;
    }
}

// ---------------------------------------------------------------------------
__global__ void transpose_wdef(const float* __restrict__ w, float* __restrict__ wtp)
{
    int idx = blockIdx.x * 256 + threadIdx.x;
    if (idx >= 9 * 128 * 128) return;
    int o = idx & 127;
    int c = (idx >> 7) & 127;
    int k = idx >> 14;
    wtp[idx] = w[((size_t)o * 128 + c) * 9 + k];
}

__global__ void dummy_k(float* p) { p[threadIdx.x] = 0.f; }

// ---------------------------------------------------------------------------
// Fused deformable conv (unchanged): 256 threads, 128 pixels, 128 oc,
// double-buffered SMEM, one barrier per iteration, gather/compute pipelined.
// ---------------------------------------------------------------------------
__global__ __launch_bounds__(256, 2) void deform_k(
    const float* __restrict__ ref, const float* __restrict__ off,
    const float* __restrict__ wtp, float* __restrict__ out)
{
    extern __shared__ __align__(16) float dsm[];
    float* s_s = dsm;           // [2][32*128] sampled values [c][px]
    float* s_w = dsm + 8192;    // [2][32*128] weights        [c][oc]

    const int tid  = threadIdx.x;
    const int pxg  = tid & 127;
    const int ch16 = (tid >> 7) * 16;
    const int wg = blockIdx.x * 16 + (pxg & 15);
    const int hg = blockIdx.y * 8  + (pxg >> 4);
    const int b  = blockIdx.z;

    const int pxc = (tid & 63) * 2;
    const int q   = tid >> 6;
    const int wc = blockIdx.x * 16 + (pxc & 15);
    const int hc = blockIdx.y * 8  + (pxc >> 4);

    u64 a2[2][16];
#pragma unroll
    for (int p = 0; p < 2; p++)
#pragma unroll
        for (int j = 0; j < 16; j++) a2[p][j] = 0ull;

    const float* offp = off + (size_t)b * 18 * HW + hg * WD + wg;
    const float* pb   = ref + (size_t)b * 128 * HW;

    float  sv[16];
    float4 wv4[4];

    auto gather = [&](int it) {
        const int k = it >> 2, chunk = it & 3;
        float dy = __ldg(offp + (2 * k)     * HW);
        float dx = __ldg(offp + (2 * k + 1) * HW);
        float py = (float)(hg + (k / 3) - 1) + dy;
        float px = (float)(wg + (k % 3) - 1) + dx;
        float y0f = floorf(py), x0f = floorf(px);
        float wy = py - y0f, wx = px - x0f;
        int y0 = (int)y0f, x0 = (int)x0f;
        int y1 = y0 + 1,   x1 = x0 + 1;
        bool vy0 = (unsigned)y0 < 128u, vy1 = (unsigned)y1 < 128u;
        bool vx0 = (unsigned)x0 < 128u, vx1 = (unsigned)x1 < 128u;
        int y0c = min(max(y0, 0), 127), y1c = min(max(y1, 0), 127);
        int x0c = min(max(x0, 0), 127), x1c = min(max(x1, 0), 127);
        float w00 = (1.f - wy) * (1.f - wx) * ((vy0 && vx0) ? 1.f : 0.f);
        float w01 = (1.f - wy) * wx         * ((vy0 && vx1) ? 1.f : 0.f);
        float w10 = wy * (1.f - wx)         * ((vy1 && vx0) ? 1.f : 0.f);
        float w11 = wy * wx                 * ((vy1 && vx1) ? 1.f : 0.f);
        int o00 = y0c * WD + x0c, o01 = y0c * WD + x1c;
        int o10 = y1c * WD + x0c, o11 = y1c * WD + x1c;

        const float* plb = pb + (size_t)(chunk * 32 + ch16) * HW;
#pragma unroll
        for (int i = 0; i < 16; i++) {
            const float* pl = plb + (size_t)i * HW;
            sv[i] = w00 * __ldg(pl + o00) + w01 * __ldg(pl + o01)
                  + w10 * __ldg(pl + o10) + w11 * __ldg(pl + o11);
        }
        const float4* wsrc = (const float4*)(wtp + (size_t)k * 16384 + chunk * 32 * 128);
#pragma unroll
        for (int j = 0; j < 4; j++) wv4[j] = __ldg(wsrc + tid + j * 256);
    };

    gather(0);

#pragma unroll 1
    for (int it = 0; it < 36; ++it) {
        const int buf = it & 1;
        float* ss = s_s + buf * 4096;
        float* sw = s_w + buf * 4096;
#pragma unroll
        for (int i = 0; i < 16; i++) ss[(ch16 + i) * 128 + pxg] = sv[i];
        {
            float4* wd4 = (float4*)sw;
#pragma unroll
            for (int j = 0; j < 4; j++) wd4[tid + j * 256] = wv4[j];
        }
        __syncthreads();

        if (it + 1 < 36) gather(it + 1);

#pragma unroll 4
        for (int c = 0; c < 32; ++c) {
            float2 s2v = *(const float2*)(ss + c * 128 + pxc);
            u64 ss0 = pk(s2v.x, s2v.x);
            u64 ss1 = pk(s2v.y, s2v.y);
            const ulonglong2* wr = (const ulonglong2*)(sw + c * 128 + q * 32);
#pragma unroll
            for (int j = 0; j < 8; j++) {
                ulonglong2 w2 = wr[j];
                a2[0][2 * j]     = fma2(w2.x, ss0, a2[0][2 * j]);
                a2[0][2 * j + 1] = fma2(w2.y, ss0, a2[0][2 * j + 1]);
                a2[1][2 * j]     = fma2(w2.x, ss1, a2[1][2 * j]);
                a2[1][2 * j + 1] = fma2(w2.y, ss1, a2[1][2 * j + 1]);
            }
        }
    }

    float* ob = out + (size_t)(b * 128 + q * 32) * HW + hc * WD + wc;
#pragma unroll
    for (int j = 0; j < 16; j++) {
        float v0, v1, u0, u1;
        upk(a2[0][j], v0, v1);
        upk(a2[1][j], u0, u1);
        float2 e; e.x = v0; e.y = u0;
        float2 f; f.x = v1; f.y = u1;
        *(float2*)(ob + (size_t)(2 * j)     * HW) = e;
        *(float2*)(ob + (size_t)(2 * j + 1) * HW) = f;
    }
}

// ---------------------------------------------------------------------------
extern "C" void kernel_launch(void* const* d_in, const int* in_sizes, int n_in,
                              void* d_out, int out_size)
{
    const float* x  = (const float*)d_in[0];  // input_features
    const float* rf = (const float*)d_in[1];  // reference_features
    const float* w1 = (const float*)d_in[2];  // w_est1 [128,256,3,3]
    const float* w2 = (const float*)d_in[3];  // w_est2 [128,128,3,3]
    const float* wo = (const float*)d_in[4];  // w_off  [18,128,3,3]
    const float* wd = (const float*)d_in[5];  // w_def  [128,128,3,3]
    float* out = (float*)d_out;

    const int B = in_sizes[0] / (128 * HW);   // 2

    float *e1, *e2, *of, *wtp, *dmy;
    cudaGetSymbolAddress((void**)&e1,  g_est1);
    cudaGetSymbolAddress((void**)&e2,  g_est2);
    cudaGetSymbolAddress((void**)&of,  g_off);
    cudaGetSymbolAddress((void**)&wtp, g_wt);
    cudaGetSymbolAddress((void**)&dmy, g_dmy);

    cudaFuncSetAttribute(deform_k,
        cudaFuncAttributeMaxDynamicSharedMemorySize, 65536);

    dim3 blk(128);

    // launches 1-3 (dummies + transpose) keep conv1 in the profiled slot
    dummy_k<<<1, 128>>>(dmy);
    dummy_k<<<1, 128>>>(dmy);
    transpose_wdef<<<(9 * 128 * 128 + 255) / 256, 256>>>(wd, wtp);
    // est = relu(conv(concat(x, rf), w_est1)) : 8h x 64w tiles, OC_B=8
    conv3x3_k<256, 8, true,  true ><<<dim3(2, 16, B * 16), blk>>>(x,  rf,      w1, e1, 128, 16);
    // est = relu(conv(est, w_est2))
    conv3x3_k<128, 8, true,  false><<<dim3(2, 16, B * 16), blk>>>(e1, nullptr, w2, e2, 128, 16);
    // offset = conv(est, w_off) : OC_B=6, 3 oc-blocks
    conv3x3_k<128, 6, false, false><<<dim3(2, 16, B * 3),  blk>>>(e2, nullptr, wo, of, 18,  3);
    // out = deform_conv2d(rf, offset, w_def)
    deform_k<<<dim3(8, 16, B), 256, 65536>>>(rf, of, wtp, out);
}

// round 9
// speedup vs baseline: 1.0975x; 1.0705x over previous
#include <cuda_runtime.h>

#define HW 16384
#define WD 128
#define PSTRIDE 4194304ull          // floats per partial slice (2*128*16384)

typedef unsigned long long u64;

// Scratch (allocation-free rule: __device__ globals)
__device__ float g_est1[2 * 128 * HW];      // 16 MB
__device__ float g_est2[2 * 128 * HW];      // 16 MB
__device__ float g_off [2 * 18  * HW];      // 2.25 MB
__device__ float g_wt  [9 * 128 * 128];     // w_def transposed to [k][c][o]
__device__ float g_part[4 * PSTRIDE];       // 64 MB: split-C partial sums
__device__ float g_dmy [128];

// ---- packed fp32x2 helpers -------------------------------------------------
__device__ __forceinline__ u64 pk(float lo, float hi) {
    u64 r; asm("mov.b64 %0, {%1, %2};" : "=l"(r) : "f"(lo), "f"(hi)); return r;
}
__device__ __forceinline__ void upk(u64 v, float& lo, float& hi) {
    asm("mov.b64 {%0, %1}, %2;" : "=f"(lo), "=f"(hi) : "l"(v));
}
__device__ __forceinline__ u64 fma2(u64 a, u64 b, u64 c) {
    u64 d; asm("fma.rn.f32x2 %0, %1, %2, %3;" : "=l"(d) : "l"(a), "l"(b), "l"(c));
    return d;
}

// ---- TMA-1D bulk + mbarrier helpers -----------------------------------------
__device__ __forceinline__ unsigned sm32(const void* p) {
    return (unsigned)__cvta_generic_to_shared(p);
}
__device__ __forceinline__ void mbar_init(unsigned mbar, unsigned cnt) {
    asm volatile("mbarrier.init.shared.b64 [%0], %1;" :: "r"(mbar), "r"(cnt) : "memory");
}
__device__ __forceinline__ void mbar_expect(unsigned mbar, unsigned bytes) {
    asm volatile("mbarrier.arrive.expect_tx.shared.b64 _, [%0], %1;"
                 :: "r"(mbar), "r"(bytes) : "memory");
}
__device__ __forceinline__ void bulk_g2s(unsigned dst, const void* src,
                                         unsigned bytes, unsigned mbar) {
    asm volatile(
        "cp.async.bulk.shared::cluster.global.mbarrier::complete_tx::bytes "
        "[%0], [%1], %2, [%3];"
        :: "r"(dst), "l"(src), "r"(bytes), "r"(mbar) : "memory");
}
__device__ __forceinline__ void mbar_wait(unsigned mbar, unsigned parity) {
    asm volatile(
        "{\n\t"
        ".reg .pred P;\n"
        "WAIT_%=:\n\t"
        "mbarrier.try_wait.parity.shared.b64 P, [%0], %1;\n\t"
        "@!P bra WAIT_%=;\n\t"
        "}"
        :: "r"(mbar), "r"(parity) : "memory");
}

// ---------------------------------------------------------------------------
// Direct 3x3 conv, stride 1, pad 1, NCHW, H=W=128, fp32x2 math, SPLIT-C:
// each block computes CHUNK input channels' partial sum and stores it to
// g_part[chunk]. 4 chunks per (tile, ocb, b). Tile 8(h) x 64(w), thread =
// 1 row x 4 cols, OC_B oc register-blocked. TMA-1D staging (10 full rows,
// 3-slot ring, distance 2, one __syncthreads per channel). No ReLU here —
// the combine kernel applies it after summing partials.
// ---------------------------------------------------------------------------
template <int C_IN, int OC_B, int CHUNK, bool CONCAT>
__global__ __launch_bounds__(128, 6) void conv3x3_k(
    const float* __restrict__ in0, const float* __restrict__ in1,
    const float* __restrict__ wt, float* __restrict__ part,
    int C_out, int n_ocb)
{
    __shared__ __align__(16) float st[3][10 * 128];       // 3 x 5120 B
    __shared__ __align__(16) u64   swd[3][OC_B * 12];
    __shared__ __align__(8)  u64   mbar[3];

    const int tid = threadIdx.x;
    const int tx  = tid & 15;          // 16 threads across W (4 px each)
    const int ty  = tid >> 4;          // 8 rows, 1 row each
    const int w0  = blockIdx.x * 64;
    const int h0  = blockIdx.y * 8;
    const int z   = blockIdx.z;
    const int chunk = z & 3;           // 4 channel chunks
    const int zz  = z >> 2;
    const int b   = zz / n_ocb;
    const int ocb = zz % n_ocb;
    const int c0  = chunk * CHUNK;

    const bool topB = (h0 == 0);
    const bool botB = (h0 == 120);
    const int  row0   = topB ? 1 : 0;
    const int  nrows  = 10 - (int)topB - (int)botB;
    const unsigned nbytes = nrows * 512;
    const int  gh0    = topB ? 0 : (h0 - 1);

    const int cq = w0 + tx * 4;
    const bool eL = (cq == 0);
    const bool eR = (cq == 124);

    // weight staging: tid < OC_B*12 handles one (o, ky, kx[0..3]) slot
    bool wv = false; long wbase = 0;
    if (tid < OC_B * 12) {
        int o  = ocb * OC_B + tid / 12;
        int ky = (tid % 12) / 4;
        int kx = tid % 4;
        wv     = (o < C_out) && (kx < 3);
        wbase  = (long)o * C_IN * 9 + ky * 3 + kx;
    }
    auto wld = [&](int c) -> float {
        return wv ? __ldg(wt + wbase + (long)c * 9) : 0.f;
    };

    auto planeof = [&](int c) -> const float* {
        if (CONCAT)
            return (c < 128) ? in0 + (size_t)(b * 128 + c) * HW
                             : in1 + (size_t)(b * 128 + (c - 128)) * HW;
        return in0 + (size_t)(b * C_IN + c) * HW;
    };

    auto issue = [&](int c, int slot) {
        if (tid == 0) {
            unsigned mb = sm32(&mbar[slot]);
            mbar_expect(mb, nbytes);
            bulk_g2s(sm32(&st[slot][row0 * 128]),
                     planeof(c) + gh0 * WD, nbytes, mb);
        }
        if (topB) st[slot][tid] = 0.f;
        if (botB) st[slot][9 * 128 + tid] = 0.f;
    };

    u64 acc[OC_B][2];
#pragma unroll
    for (int o = 0; o < OC_B; o++) { acc[o][0] = 0ull; acc[o][1] = 0ull; }

    if (tid == 0) {
#pragma unroll
        for (int j = 0; j < 3; j++) mbar_init(sm32(&mbar[j]), 1);
    }
    __syncthreads();

    issue(c0, 0);
    issue(c0 + 1, 1);
    float wreg;
    {
        float t0 = wld(c0);
        if (tid < OC_B * 12) swd[0][tid] = pk(t0, t0);
        wreg = wld(c0 + 1);
    }
    __syncthreads();

#pragma unroll 1
    for (int s = 0; s < CHUNK; ++s) {
        const int slot = s % 3;
        mbar_wait(sm32(&mbar[slot]), (unsigned)((s / 3) & 1));

        const float* sbuf = st[slot];
        const u64*   wrow = swd[slot];
#pragma unroll
        for (int ky = 0; ky < 3; ky++) {
            const float* base = sbuf + (ty + ky) * 128;
            float  l  = eL ? 0.f : base[cq - 1];
            float4 X  = *(const float4*)(base + cq);
            float  rr = eR ? 0.f : base[cq + 4];
            u64 P0 = pk(l,   X.x);
            u64 P1 = pk(X.x, X.y);
            u64 P2 = pk(X.y, X.z);
            u64 P3 = pk(X.z, X.w);
            u64 P4 = pk(X.w, rr);
#pragma unroll
            for (int o = 0; o < OC_B; o++) {
                ulonglong2 w01 = *(const ulonglong2*)(wrow + o * 12 + ky * 4);
                u64        w2v = wrow[o * 12 + ky * 4 + 2];
                acc[o][0] = fma2(P0, w01.x, acc[o][0]);
                acc[o][1] = fma2(P2, w01.x, acc[o][1]);
                acc[o][0] = fma2(P1, w01.y, acc[o][0]);
                acc[o][1] = fma2(P3, w01.y, acc[o][1]);
                acc[o][0] = fma2(P2, w2v,   acc[o][0]);
                acc[o][1] = fma2(P4, w2v,   acc[o][1]);
            }
        }

        if (s + 1 < CHUNK) {
            if (tid < OC_B * 12) swd[(s + 1) % 3][tid] = pk(wreg, wreg);
            wreg = (s + 2 < CHUNK) ? wld(c0 + s + 2) : 0.f;
        }
        __syncthreads();
        if (s + 2 < CHUNK) issue(c0 + s + 2, (s + 2) % 3);
    }

    const int ph = h0 + ty;
    float* pb = part + (size_t)chunk * PSTRIDE;
#pragma unroll
    for (int o = 0; o < OC_B; o++) {
        int oc = ocb * OC_B + o;
        if (oc >= C_out) break;
        float* op = pb + (size_t)(b * C_out + oc) * HW + ph * WD + cq;
        float4 v;
        upk(acc[o][0], v.x, v.y);
        upk(acc[o][1], v.z, v.w);
        *(float4*)op = v;
    }
}

// ---------------------------------------------------------------------------
// Combine split-C partials: dst = (relu of) sum of 4 partial slices.
// ---------------------------------------------------------------------------
template <bool RELU>
__global__ __launch_bounds__(256) void combine_k(
    const float* __restrict__ part, float* __restrict__ dst, int n4)
{
    int i = blockIdx.x * 256 + threadIdx.x;
    if (i >= n4) return;
    float4 s = __ldg((const float4*)part + i);
#pragma unroll
    for (int j = 1; j < 4; j++) {
        float4 t = __ldg((const float4*)(part + (size_t)j * PSTRIDE) + i);
        s.x += t.x; s.y += t.y; s.z += t.z; s.w += t.w;
    }
    if (RELU) {
        s.x = fmaxf(s.x, 0.f); s.y = fmaxf(s.y, 0.f);
        s.z = fmaxf(s.z, 0.f); s.w = fmaxf(s.w, 0.f);
    }
    ((float4*)dst)[i] = s;
}

// ---------------------------------------------------------------------------
__global__ void transpose_wdef(const float* __restrict__ w, float* __restrict__ wtp)
{
    int idx = blockIdx.x * 256 + threadIdx.x;
    if (idx >= 9 * 128 * 128) return;
    int o = idx & 127;
    int c = (idx >> 7) & 127;
    int k = idx >> 14;
    wtp[idx] = w[((size_t)o * 128 + c) * 9 + k];
}

__global__ void dummy_k(float* p) { p[threadIdx.x] = 0.f; }

// ---------------------------------------------------------------------------
// Fused deformable conv (unchanged): 256 threads, 128 pixels, 128 oc,
// double-buffered SMEM, one barrier per iteration, gather/compute pipelined.
// ---------------------------------------------------------------------------
__global__ __launch_bounds__(256, 2) void deform_k(
    const float* __restrict__ ref, const float* __restrict__ off,
    const float* __restrict__ wtp, float* __restrict__ out)
{
    extern __shared__ __align__(16) float dsm[];
    float* s_s = dsm;           // [2][32*128] sampled values [c][px]
    float* s_w = dsm + 8192;    // [2][32*128] weights        [c][oc]

    const int tid  = threadIdx.x;
    const int pxg  = tid & 127;
    const int ch16 = (tid >> 7) * 16;
    const int wg = blockIdx.x * 16 + (pxg & 15);
    const int hg = blockIdx.y * 8  + (pxg >> 4);
    const int b  = blockIdx.z;

    const int pxc = (tid & 63) * 2;
    const int q   = tid >> 6;
    const int wc = blockIdx.x * 16 + (pxc & 15);
    const int hc = blockIdx.y * 8  + (pxc >> 4);

    u64 a2[2][16];
#pragma unroll
    for (int p = 0; p < 2; p++)
#pragma unroll
        for (int j = 0; j < 16; j++) a2[p][j] = 0ull;

    const float* offp = off + (size_t)b * 18 * HW + hg * WD + wg;
    const float* pb   = ref + (size_t)b * 128 * HW;

    float  sv[16];
    float4 wv4[4];

    auto gather = [&](int it) {
        const int k = it >> 2, chunk = it & 3;
        float dy = __ldg(offp + (2 * k)     * HW);
        float dx = __ldg(offp + (2 * k + 1) * HW);
        float py = (float)(hg + (k / 3) - 1) + dy;
        float px = (float)(wg + (k % 3) - 1) + dx;
        float y0f = floorf(py), x0f = floorf(px);
        float wy = py - y0f, wx = px - x0f;
        int y0 = (int)y0f, x0 = (int)x0f;
        int y1 = y0 + 1,   x1 = x0 + 1;
        bool vy0 = (unsigned)y0 < 128u, vy1 = (unsigned)y1 < 128u;
        bool vx0 = (unsigned)x0 < 128u, vx1 = (unsigned)x1 < 128u;
        int y0c = min(max(y0, 0), 127), y1c = min(max(y1, 0), 127);
        int x0c = min(max(x0, 0), 127), x1c = min(max(x1, 0), 127);
        float w00 = (1.f - wy) * (1.f - wx) * ((vy0 && vx0) ? 1.f : 0.f);
        float w01 = (1.f - wy) * wx         * ((vy0 && vx1) ? 1.f : 0.f);
        float w10 = wy * (1.f - wx)         * ((vy1 && vx0) ? 1.f : 0.f);
        float w11 = wy * wx                 * ((vy1 && vx1) ? 1.f : 0.f);
        int o00 = y0c * WD + x0c, o01 = y0c * WD + x1c;
        int o10 = y1c * WD + x0c, o11 = y1c * WD + x1c;

        const float* plb = pb + (size_t)(chunk * 32 + ch16) * HW;
#pragma unroll
        for (int i = 0; i < 16; i++) {
            const float* pl = plb + (size_t)i * HW;
            sv[i] = w00 * __ldg(pl + o00) + w01 * __ldg(pl + o01)
                  + w10 * __ldg(pl + o10) + w11 * __ldg(pl + o11);
        }
        const float4* wsrc = (const float4*)(wtp + (size_t)k * 16384 + chunk * 32 * 128);
#pragma unroll
        for (int j = 0; j < 4; j++) wv4[j] = __ldg(wsrc + tid + j * 256);
    };

    gather(0);

#pragma unroll 1
    for (int it = 0; it < 36; ++it) {
        const int buf = it & 1;
        float* ss = s_s + buf * 4096;
        float* sw = s_w + buf * 4096;
#pragma unroll
        for (int i = 0; i < 16; i++) ss[(ch16 + i) * 128 + pxg] = sv[i];
        {
            float4* wd4 = (float4*)sw;
#pragma unroll
            for (int j = 0; j < 4; j++) wd4[tid + j * 256] = wv4[j];
        }
        __syncthreads();

        if (it + 1 < 36) gather(it + 1);

#pragma unroll 4
        for (int c = 0; c < 32; ++c) {
            float2 s2v = *(const float2*)(ss + c * 128 + pxc);
            u64 ss0 = pk(s2v.x, s2v.x);
            u64 ss1 = pk(s2v.y, s2v.y);
            const ulonglong2* wr = (const ulonglong2*)(sw + c * 128 + q * 32);
#pragma unroll
            for (int j = 0; j < 8; j++) {
                ulonglong2 w2 = wr[j];
                a2[0][2 * j]     = fma2(w2.x, ss0, a2[0][2 * j]);
                a2[0][2 * j + 1] = fma2(w2.y, ss0, a2[0][2 * j + 1]);
                a2[1][2 * j]     = fma2(w2.x, ss1, a2[1][2 * j]);
                a2[1][2 * j + 1] = fma2(w2.y, ss1, a2[1][2 * j + 1]);
            }
        }
    }

    float* ob = out + (size_t)(b * 128 + q * 32) * HW + hc * WD + wc;
#pragma unroll
    for (int j = 0; j < 16; j++) {
        float v0, v1, u0, u1;
        upk(a2[0][j], v0, v1);
        upk(a2[1][j], u0, u1);
        float2 e; e.x = v0; e.y = u0;
        float2 f; f.x = v1; f.y = u1;
        *(float2*)(ob + (size_t)(2 * j)     * HW) = e;
        *(float2*)(ob + (size_t)(2 * j + 1) * HW) = f;
    }
}

// ---------------------------------------------------------------------------
extern "C" void kernel_launch(void* const* d_in, const int* in_sizes, int n_in,
                              void* d_out, int out_size)
{
    const float* x  = (const float*)d_in[0];  // input_features
    const float* rf = (const float*)d_in[1];  // reference_features
    const float* w1 = (const float*)d_in[2];  // w_est1 [128,256,3,3]
    const float* w2 = (const float*)d_in[3];  // w_est2 [128,128,3,3]
    const float* wo = (const float*)d_in[4];  // w_off  [18,128,3,3]
    const float* wd = (const float*)d_in[5];  // w_def  [128,128,3,3]
    float* out = (float*)d_out;

    const int B = in_sizes[0] / (128 * HW);   // 2

    float *e1, *e2, *of, *wtp, *prt, *dmy;
    cudaGetSymbolAddress((void**)&e1,  g_est1);
    cudaGetSymbolAddress((void**)&e2,  g_est2);
    cudaGetSymbolAddress((void**)&of,  g_off);
    cudaGetSymbolAddress((void**)&wtp, g_wt);
    cudaGetSymbolAddress((void**)&prt, g_part);
    cudaGetSymbolAddress((void**)&dmy, g_dmy);

    cudaFuncSetAttribute(deform_k,
        cudaFuncAttributeMaxDynamicSharedMemorySize, 65536);

    dim3 blk(128);
    const int n4_full = 2 * 128 * HW / 4;     // e1 / e2 combine size (float4)
    const int n4_off  = 2 * 18  * HW / 4;

    // launches 1-3 (dummies + transpose) keep conv1 in the profiled slot
    dummy_k<<<1, 128>>>(dmy);
    dummy_k<<<1, 128>>>(dmy);
    transpose_wdef<<<(9 * 128 * 128 + 255) / 256, 256>>>(wd, wtp);
    // conv1 partials: 4 chunks x 64 ch -> g_part    (z = b*16*4 + ocb*4 + chunk)
    conv3x3_k<256, 8, 64, true ><<<dim3(2, 16, B * 16 * 4), blk>>>(x, rf, w1, prt, 128, 16);
    combine_k<true ><<<(n4_full + 255) / 256, 256>>>(prt, e1, n4_full);
    // conv2 partials: 4 chunks x 32 ch
    conv3x3_k<128, 8, 32, false><<<dim3(2, 16, B * 16 * 4), blk>>>(e1, nullptr, w2, prt, 128, 16);
    combine_k<true ><<<(n4_full + 255) / 256, 256>>>(prt, e2, n4_full);
    // offset conv partials: 4 chunks x 32 ch
    conv3x3_k<128, 6, 32, false><<<dim3(2, 16, B * 3 * 4),  blk>>>(e2, nullptr, wo, prt, 18, 3);
    combine_k<false><<<(n4_off + 255) / 256, 256>>>(prt, of, n4_off);
    // out = deform_conv2d(rf, offset, w_def)
    deform_k<<<dim3(8, 16, B), 256, 65536>>>(rf, of, wtp, out);
}

// round 10
// speedup vs baseline: 1.1329x; 1.0322x over previous
#include <cuda_runtime.h>

#define HW 16384
#define WD 128
#define PSTRIDE 4194304ull          // floats per partial slice (2*128*16384)

typedef unsigned long long u64;

// Scratch (allocation-free rule: __device__ globals)
__device__ float g_est1[2 * 128 * HW];      // 16 MB
__device__ float g_est2[2 * 128 * HW];      // 16 MB
__device__ float g_off [2 * 18  * HW];      // 2.25 MB
__device__ float g_wt  [9 * 128 * 128];     // w_def transposed to [k][c][o]
__device__ float g_part[4 * PSTRIDE];       // 64 MB: split-C partial sums
__device__ float g_dmy [128];

// ---- packed fp32x2 helpers -------------------------------------------------
__device__ __forceinline__ u64 pk(float lo, float hi) {
    u64 r; asm("mov.b64 %0, {%1, %2};" : "=l"(r) : "f"(lo), "f"(hi)); return r;
}
__device__ __forceinline__ void upk(u64 v, float& lo, float& hi) {
    asm("mov.b64 {%0, %1}, %2;" : "=f"(lo), "=f"(hi) : "l"(v));
}
__device__ __forceinline__ u64 fma2(u64 a, u64 b, u64 c) {
    u64 d; asm("fma.rn.f32x2 %0, %1, %2, %3;" : "=l"(d) : "l"(a), "l"(b), "l"(c));
    return d;
}

// ---- TMA-1D bulk + mbarrier helpers -----------------------------------------
__device__ __forceinline__ unsigned sm32(const void* p) {
    return (unsigned)__cvta_generic_to_shared(p);
}
__device__ __forceinline__ void mbar_init(unsigned mbar, unsigned cnt) {
    asm volatile("mbarrier.init.shared.b64 [%0], %1;" :: "r"(mbar), "r"(cnt) : "memory");
}
__device__ __forceinline__ void mbar_expect(unsigned mbar, unsigned bytes) {
    asm volatile("mbarrier.arrive.expect_tx.shared.b64 _, [%0], %1;"
                 :: "r"(mbar), "r"(bytes) : "memory");
}
__device__ __forceinline__ void bulk_g2s(unsigned dst, const void* src,
                                         unsigned bytes, unsigned mbar) {
    asm volatile(
        "cp.async.bulk.shared::cluster.global.mbarrier::complete_tx::bytes "
        "[%0], [%1], %2, [%3];"
        :: "r"(dst), "l"(src), "r"(bytes), "r"(mbar) : "memory");
}
__device__ __forceinline__ void mbar_wait(unsigned mbar, unsigned parity) {
    asm volatile(
        "{\n\t"
        ".reg .pred P;\n"
        "WAIT_%=:\n\t"
        "mbarrier.try_wait.parity.shared.b64 P, [%0], %1;\n\t"
        "@!P bra WAIT_%=;\n\t"
        "}"
        :: "r"(mbar), "r"(parity) : "memory");
}

// ---------------------------------------------------------------------------
// Direct 3x3 conv, stride 1, pad 1, NCHW, H=W=128, fp32x2, SPLIT-C partials.
// Tile = 8 rows x FULL 128-wide row; thread = 1 row x 8 cols (tx*8).
// 288 fma2 : 36 LDS per channel (2x better FMA:LDS than 4-px version).
// 4-slot TMA-1D ring, distance 3, channel loop unrolled x4 (compile-time
// slots -> hoisted SMEM addressing). One __syncthreads per channel.
// ---------------------------------------------------------------------------
template <int C_IN, int OC_B, int CHUNK, bool CONCAT>
__global__ __launch_bounds__(128, 4) void conv3x3_k(
    const float* __restrict__ in0, const float* __restrict__ in1,
    const float* __restrict__ wt, float* __restrict__ part,
    int C_out, int n_ocb)
{
    __shared__ __align__(8)  u64   mbar[4];
    __shared__ __align__(16) u64   swd[4][OC_B * 12];
    __shared__ __align__(16) float st[4][10 * 128];      // 4 x 5120 B

    const int tid = threadIdx.x;
    const int tx  = tid & 15;          // 16 threads across W (8 px each)
    const int ty  = tid >> 4;          // 8 rows, 1 row each
    const int h0  = blockIdx.y * 8;
    const int z   = blockIdx.z;
    const int chunk = z & 3;           // 4 channel chunks
    const int zz  = z >> 2;
    const int b   = zz / n_ocb;
    const int ocb = zz % n_ocb;
    const int c0  = chunk * CHUNK;

    const bool topB = (h0 == 0);
    const bool botB = (h0 == 120);
    const int  row0   = topB ? 1 : 0;
    const int  nrows  = 10 - (int)topB - (int)botB;
    const unsigned nbytes = nrows * 512;
    const int  gh0    = topB ? 0 : (h0 - 1);

    const int cq = tx * 8;             // first out col of thread
    const bool eL = (tx == 0);
    const bool eR = (tx == 15);

    // weight staging: tid < OC_B*12 handles one (o, ky, kx[0..3]) slot
    bool wv = false; long wbase = 0;
    if (tid < OC_B * 12) {
        int o  = ocb * OC_B + tid / 12;
        int ky = (tid % 12) / 4;
        int kx = tid % 4;
        wv     = (o < C_out) && (kx < 3);
        wbase  = (long)o * C_IN * 9 + ky * 3 + kx;
    }
    auto wld = [&](int c) -> float {
        return wv ? __ldg(wt + wbase + (long)c * 9) : 0.f;
    };

    auto planeof = [&](int c) -> const float* {
        if (CONCAT)
            return (c < 128) ? in0 + (size_t)(b * 128 + c) * HW
                             : in1 + (size_t)(b * 128 + (c - 128)) * HW;
        return in0 + (size_t)(b * C_IN + c) * HW;
    };

    auto issue = [&](int c, int slot) {
        if (tid == 0) {
            unsigned mb = sm32(&mbar[slot]);
            mbar_expect(mb, nbytes);
            bulk_g2s(sm32(&st[slot][row0 * 128]),
                     planeof(c) + gh0 * WD, nbytes, mb);
        }
        if (topB) st[slot][tid] = 0.f;
        if (botB) st[slot][9 * 128 + tid] = 0.f;
    };

    u64 acc[OC_B][4];
#pragma unroll
    for (int o = 0; o < OC_B; o++)
#pragma unroll
        for (int m = 0; m < 4; m++) acc[o][m] = 0ull;

    if (tid == 0) {
#pragma unroll
        for (int j = 0; j < 4; j++) mbar_init(sm32(&mbar[j]), 1);
    }
    __syncthreads();

    issue(c0,     0);
    issue(c0 + 1, 1);
    issue(c0 + 2, 2);
    float wreg;
    {
        float t0 = wld(c0);
        if (tid < OC_B * 12) swd[0][tid] = pk(t0, t0);
        wreg = wld(c0 + 1);
    }
    __syncthreads();

    const int NG = CHUNK / 4;
    unsigned par = 0;
#pragma unroll 1
    for (int g = 0; g < NG; ++g) {
#pragma unroll
        for (int j = 0; j < 4; j++) {
            const int s = g * 4 + j;               // channel within chunk
            mbar_wait(sm32(&mbar[j]), par);

            const float* sbuf = st[j];
            const u64*   wbuf = swd[j];
#pragma unroll
            for (int ky = 0; ky < 3; ky++) {
                const float* base = sbuf + (ty + ky) * 128 + cq;
                float  l  = eL ? 0.f : base[-1];
                float4 X  = *(const float4*)(base);
                float4 Y  = *(const float4*)(base + 4);
                float  rr = eR ? 0.f : base[8];
                u64 P0 = pk(l,   X.x);
                u64 P1 = pk(X.x, X.y);
                u64 P2 = pk(X.y, X.z);
                u64 P3 = pk(X.z, X.w);
                u64 P4 = pk(X.w, Y.x);
                u64 P5 = pk(Y.x, Y.y);
                u64 P6 = pk(Y.y, Y.z);
                u64 P7 = pk(Y.z, Y.w);
                u64 P8 = pk(Y.w, rr);
#pragma unroll
                for (int o = 0; o < OC_B; o++) {
                    ulonglong2 w01 = *(const ulonglong2*)(wbuf + o * 12 + ky * 4);
                    u64        w2v = wbuf[o * 12 + ky * 4 + 2];
                    acc[o][0] = fma2(P0, w01.x, acc[o][0]);
                    acc[o][1] = fma2(P2, w01.x, acc[o][1]);
                    acc[o][2] = fma2(P4, w01.x, acc[o][2]);
                    acc[o][3] = fma2(P6, w01.x, acc[o][3]);
                    acc[o][0] = fma2(P1, w01.y, acc[o][0]);
                    acc[o][1] = fma2(P3, w01.y, acc[o][1]);
                    acc[o][2] = fma2(P5, w01.y, acc[o][2]);
                    acc[o][3] = fma2(P7, w01.y, acc[o][3]);
                    acc[o][0] = fma2(P2, w2v,   acc[o][0]);
                    acc[o][1] = fma2(P4, w2v,   acc[o][1]);
                    acc[o][2] = fma2(P6, w2v,   acc[o][2]);
                    acc[o][3] = fma2(P8, w2v,   acc[o][3]);
                }
            }

            if (s + 1 < CHUNK) {
                if (tid < OC_B * 12) swd[(j + 1) & 3][tid] = pk(wreg, wreg);
                wreg = (s + 2 < CHUNK) ? wld(c0 + s + 2) : 0.f;
            }
            __syncthreads();           // readers of slot (j+3)&3 done (ch s-1);
                                       // swd[s+1] published
            if (s + 3 < CHUNK) issue(c0 + s + 3, (j + 3) & 3);
        }
        par ^= 1;
    }

    const int ph = h0 + ty;
    float* pb = part + (size_t)chunk * PSTRIDE;
#pragma unroll
    for (int o = 0; o < OC_B; o++) {
        int oc = ocb * OC_B + o;
        if (oc >= C_out) break;
        float* op = pb + (size_t)(b * C_out + oc) * HW + ph * WD + cq;
        float4 v0, v1;
        upk(acc[o][0], v0.x, v0.y);
        upk(acc[o][1], v0.z, v0.w);
        upk(acc[o][2], v1.x, v1.y);
        upk(acc[o][3], v1.z, v1.w);
        *(float4*)op       = v0;
        *(float4*)(op + 4) = v1;
    }
}

// ---------------------------------------------------------------------------
// Combine split-C partials: dst = (relu of) sum of 4 partial slices.
// ---------------------------------------------------------------------------
template <bool RELU>
__global__ __launch_bounds__(256) void combine_k(
    const float* __restrict__ part, float* __restrict__ dst, int n4)
{
    int i = blockIdx.x * 256 + threadIdx.x;
    if (i >= n4) return;
    float4 s = __ldg((const float4*)part + i);
#pragma unroll
    for (int j = 1; j < 4; j++) {
        float4 t = __ldg((const float4*)(part + (size_t)j * PSTRIDE) + i);
        s.x += t.x; s.y += t.y; s.z += t.z; s.w += t.w;
    }
    if (RELU) {
        s.x = fmaxf(s.x, 0.f); s.y = fmaxf(s.y, 0.f);
        s.z = fmaxf(s.z, 0.f); s.w = fmaxf(s.w, 0.f);
    }
    ((float4*)dst)[i] = s;
}

// ---------------------------------------------------------------------------
__global__ void transpose_wdef(const float* __restrict__ w, float* __restrict__ wtp)
{
    int idx = blockIdx.x * 256 + threadIdx.x;
    if (idx >= 9 * 128 * 128) return;
    int o = idx & 127;
    int c = (idx >> 7) & 127;
    int k = idx >> 14;
    wtp[idx] = w[((size_t)o * 128 + c) * 9 + k];
}

__global__ void dummy_k(float* p) { p[threadIdx.x] = 0.f; }

// ---------------------------------------------------------------------------
// Fused deformable conv (unchanged): 256 threads, 128 pixels, 128 oc,
// double-buffered SMEM, one barrier per iteration, gather/compute pipelined.
// ---------------------------------------------------------------------------
__global__ __launch_bounds__(256, 2) void deform_k(
    const float* __restrict__ ref, const float* __restrict__ off,
    const float* __restrict__ wtp, float* __restrict__ out)
{
    extern __shared__ __align__(16) float dsm[];
    float* s_s = dsm;           // [2][32*128] sampled values [c][px]
    float* s_w = dsm + 8192;    // [2][32*128] weights        [c][oc]

    const int tid  = threadIdx.x;
    const int pxg  = tid & 127;
    const int ch16 = (tid >> 7) * 16;
    const int wg = blockIdx.x * 16 + (pxg & 15);
    const int hg = blockIdx.y * 8  + (pxg >> 4);
    const int b  = blockIdx.z;

    const int pxc = (tid & 63) * 2;
    const int q   = tid >> 6;
    const int wc = blockIdx.x * 16 + (pxc & 15);
    const int hc = blockIdx.y * 8  + (pxc >> 4);

    u64 a2[2][16];
#pragma unroll
    for (int p = 0; p < 2; p++)
#pragma unroll
        for (int j = 0; j < 16; j++) a2[p][j] = 0ull;

    const float* offp = off + (size_t)b * 18 * HW + hg * WD + wg;
    const float* pb   = ref + (size_t)b * 128 * HW;

    float  sv[16];
    float4 wv4[4];

    auto gather = [&](int it) {
        const int k = it >> 2, chunk = it & 3;
        float dy = __ldg(offp + (2 * k)     * HW);
        float dx = __ldg(offp + (2 * k + 1) * HW);
        float py = (float)(hg + (k / 3) - 1) + dy;
        float px = (float)(wg + (k % 3) - 1) + dx;
        float y0f = floorf(py), x0f = floorf(px);
        float wy = py - y0f, wx = px - x0f;
        int y0 = (int)y0f, x0 = (int)x0f;
        int y1 = y0 + 1,   x1 = x0 + 1;
        bool vy0 = (unsigned)y0 < 128u, vy1 = (unsigned)y1 < 128u;
        bool vx0 = (unsigned)x0 < 128u, vx1 = (unsigned)x1 < 128u;
        int y0c = min(max(y0, 0), 127), y1c = min(max(y1, 0), 127);
        int x0c = min(max(x0, 0), 127), x1c = min(max(x1, 0), 127);
        float w00 = (1.f - wy) * (1.f - wx) * ((vy0 && vx0) ? 1.f : 0.f);
        float w01 = (1.f - wy) * wx         * ((vy0 && vx1) ? 1.f : 0.f);
        float w10 = wy * (1.f - wx)         * ((vy1 && vx0) ? 1.f : 0.f);
        float w11 = wy * wx                 * ((vy1 && vx1) ? 1.f : 0.f);
        int o00 = y0c * WD + x0c, o01 = y0c * WD + x1c;
        int o10 = y1c * WD + x0c, o11 = y1c * WD + x1c;

        const float* plb = pb + (size_t)(chunk * 32 + ch16) * HW;
#pragma unroll
        for (int i = 0; i < 16; i++) {
            const float* pl = plb + (size_t)i * HW;
            sv[i] = w00 * __ldg(pl + o00) + w01 * __ldg(pl + o01)
                  + w10 * __ldg(pl + o10) + w11 * __ldg(pl + o11);
        }
        const float4* wsrc = (const float4*)(wtp + (size_t)k * 16384 + chunk * 32 * 128);
#pragma unroll
        for (int j = 0; j < 4; j++) wv4[j] = __ldg(wsrc + tid + j * 256);
    };

    gather(0);

#pragma unroll 1
    for (int it = 0; it < 36; ++it) {
        const int buf = it & 1;
        float* ss = s_s + buf * 4096;
        float* sw = s_w + buf * 4096;
#pragma unroll
        for (int i = 0; i < 16; i++) ss[(ch16 + i) * 128 + pxg] = sv[i];
        {
            float4* wd4 = (float4*)sw;
#pragma unroll
            for (int j = 0; j < 4; j++) wd4[tid + j * 256] = wv4[j];
        }
        __syncthreads();

        if (it + 1 < 36) gather(it + 1);

#pragma unroll 4
        for (int c = 0; c < 32; ++c) {
            float2 s2v = *(const float2*)(ss + c * 128 + pxc);
            u64 ss0 = pk(s2v.x, s2v.x);
            u64 ss1 = pk(s2v.y, s2v.y);
            const ulonglong2* wr = (const ulonglong2*)(sw + c * 128 + q * 32);
#pragma unroll
            for (int j = 0; j < 8; j++) {
                ulonglong2 w2 = wr[j];
                a2[0][2 * j]     = fma2(w2.x, ss0, a2[0][2 * j]);
                a2[0][2 * j + 1] = fma2(w2.y, ss0, a2[0][2 * j + 1]);
                a2[1][2 * j]     = fma2(w2.x, ss1, a2[1][2 * j]);
                a2[1][2 * j + 1] = fma2(w2.y, ss1, a2[1][2 * j + 1]);
            }
        }
    }

    float* ob = out + (size_t)(b * 128 + q * 32) * HW + hc * WD + wc;
#pragma unroll
    for (int j = 0; j < 16; j++) {
        float v0, v1, u0, u1;
        upk(a2[0][j], v0, v1);
        upk(a2[1][j], u0, u1);
        float2 e; e.x = v0; e.y = u0;
        float2 f; f.x = v1; f.y = u1;
        *(float2*)(ob + (size_t)(2 * j)     * HW) = e;
        *(float2*)(ob + (size_t)(2 * j + 1) * HW) = f;
    }
}

// ---------------------------------------------------------------------------
extern "C" void kernel_launch(void* const* d_in, const int* in_sizes, int n_in,
                              void* d_out, int out_size)
{
    const float* x  = (const float*)d_in[0];  // input_features
    const float* rf = (const float*)d_in[1];  // reference_features
    const float* w1 = (const float*)d_in[2];  // w_est1 [128,256,3,3]
    const float* w2 = (const float*)d_in[3];  // w_est2 [128,128,3,3]
    const float* wo = (const float*)d_in[4];  // w_off  [18,128,3,3]
    const float* wd = (const float*)d_in[5];  // w_def  [128,128,3,3]
    float* out = (float*)d_out;

    const int B = in_sizes[0] / (128 * HW);   // 2

    float *e1, *e2, *of, *wtp, *prt, *dmy;
    cudaGetSymbolAddress((void**)&e1,  g_est1);
    cudaGetSymbolAddress((void**)&e2,  g_est2);
    cudaGetSymbolAddress((void**)&of,  g_off);
    cudaGetSymbolAddress((void**)&wtp, g_wt);
    cudaGetSymbolAddress((void**)&prt, g_part);
    cudaGetSymbolAddress((void**)&dmy, g_dmy);

    cudaFuncSetAttribute(deform_k,
        cudaFuncAttributeMaxDynamicSharedMemorySize, 65536);

    dim3 blk(128);
    const int n4_full = 2 * 128 * HW / 4;     // e1 / e2 combine size (float4)
    const int n4_off  = 2 * 18  * HW / 4;

    // launches 1-3 (dummies + transpose) keep conv1 in the profiled slot
    dummy_k<<<1, 128>>>(dmy);
    dummy_k<<<1, 128>>>(dmy);
    transpose_wdef<<<(9 * 128 * 128 + 255) / 256, 256>>>(wd, wtp);
    // conv1 partials: 4 chunks x 64 ch (z = ((b*16)+ocb)*4 + chunk)
    conv3x3_k<256, 8, 64, true ><<<dim3(1, 16, B * 16 * 4), blk>>>(x, rf, w1, prt, 128, 16);
    combine_k<true ><<<(n4_full + 255) / 256, 256>>>(prt, e1, n4_full);
    // conv2 partials: 4 chunks x 32 ch
    conv3x3_k<128, 8, 32, false><<<dim3(1, 16, B * 16 * 4), blk>>>(e1, nullptr, w2, prt, 128, 16);
    combine_k<true ><<<(n4_full + 255) / 256, 256>>>(prt, e2, n4_full);
    // offset conv partials: 4 chunks x 32 ch, OC_B=6 x 3 blocks
    conv3x3_k<128, 6, 32, false><<<dim3(1, 16, B * 3 * 4),  blk>>>(e2, nullptr, wo, prt, 18, 3);
    combine_k<false><<<(n4_off + 255) / 256, 256>>>(prt, of, n4_off);
    // out = deform_conv2d(rf, offset, w_def)
    deform_k<<<dim3(8, 16, B), 256, 65536>>>(rf, of, wtp, out);
}